// round 1
// baseline (speedup 1.0000x reference)
#include <cuda_runtime.h>
#include <cuda_bf16.h>
#include <math.h>

#define L_ 256
#define D_ 300
#define S_ 16
#define K_ 16
#define E_ 2048
#define C_ 7
#define NEG_ (-1000000000.0f)

// ---------------- scratch (static device globals; no runtime alloc) --------
__device__ float g_Y0[L_ * D_];
__device__ float g_Y1[L_ * D_];
__device__ float g_Q[L_ * D_];
__device__ float g_Km[L_ * D_];
__device__ float g_Vm[L_ * D_];
__device__ float g_xws[L_ * D_];
__device__ float g_attout[L_ * D_];
__device__ float g_rel[L_ * D_];
__device__ float g_norm[L_];
__device__ float g_feat[L_ * 3 * D_];
__device__ float g_nodes[L_ * 3 * S_ * D_];   // [L,48,300]
__device__ float g_scoreb[L_ * 3 * S_];
__device__ int   g_nmask[L_ * 3 * S_];
__device__ float g_h1[L_ * D_];

__device__ __forceinline__ float wred(float v) {
#pragma unroll
    for (int o = 16; o; o >>= 1) v += __shfl_xor_sync(0xFFFFFFFFu, v, o);
    return v;
}

// ---------------- generic tiled GEMM: C = act(A[MxK] @ B[KxN] + bias) ------
__global__ void gemm_kernel(const float* __restrict__ A, const float* __restrict__ B,
                            const float* __restrict__ bias, float* __restrict__ C,
                            int M, int N, int K, int ldc, int relu)
{
    __shared__ float As[32][33];
    __shared__ float Bs[32][33];
    int tx = threadIdx.x & 31;
    int ty = threadIdx.x >> 5;      // 0..7
    int row0 = blockIdx.y * 32;
    int col  = blockIdx.x * 32 + tx;
    float acc[4] = {0.f, 0.f, 0.f, 0.f};
    for (int k0 = 0; k0 < K; k0 += 32) {
#pragma unroll
        for (int i = 0; i < 4; i++) {
            int r = ty + 8 * i;
            int ar = row0 + r, ac = k0 + tx;
            As[r][tx] = (ar < M && ac < K) ? A[ar * K + ac] : 0.f;
            int br = k0 + r;
            Bs[r][tx] = (br < K && col < N) ? B[br * N + col] : 0.f;
        }
        __syncthreads();
#pragma unroll
        for (int kk = 0; kk < 32; kk++) {
            float bv = Bs[kk][tx];
#pragma unroll
            for (int i = 0; i < 4; i++) acc[i] += As[ty + 8 * i][kk] * bv;
        }
        __syncthreads();
    }
    if (col < N) {
        float bv = bias ? bias[col] : 0.f;
#pragma unroll
        for (int i = 0; i < 4; i++) {
            int r = row0 + ty + 8 * i;
            if (r < M) {
                float v = acc[i] + bv;
                if (relu) v = fmaxf(v, 0.f);
                C[r * ldc + col] = v;
            }
        }
    }
}

// ---------------- RGCN: feat[:,0:300] = xws + segment_sum(msg) -------------
// deterministic edge scan per destination row
__global__ void rgcn_kernel(const int* __restrict__ esrc, const int* __restrict__ edst,
                            const int* __restrict__ etyp, const float* __restrict__ comp)
{
    int l = blockIdx.x;
    int tid = threadIdx.x;        // 320 threads
    __shared__ int s_src[256], s_dst[256], s_typ[256];
    float acc = 0.f;
    for (int base = 0; base < E_; base += 256) {
        if (tid < 256) {
            s_src[tid] = esrc[base + tid];
            s_dst[tid] = edst[base + tid];
            s_typ[tid] = etyp[base + tid];
        }
        __syncthreads();
        if (tid < D_) {
            for (int e = 0; e < 256; e++) {
                if (s_dst[e] == l) {
                    int s = s_src[e], t = s_typ[e];
                    acc += comp[t * 2] * g_Y0[s * D_ + tid] + comp[t * 2 + 1] * g_Y1[s * D_ + tid];
                }
            }
        }
        __syncthreads();
    }
    if (tid < D_) g_feat[l * 3 * D_ + tid] = g_xws[l * D_ + tid] + acc;
}

// ---------------- windowed attention (query = center only) ----------------
__global__ void relatt_kernel()
{
    int l = blockIdx.x;
    int tid = threadIdx.x;        // 192 threads, 6 warps
    int wid = tid >> 5, lane = tid & 31;
    __shared__ float sS[2][3];
    __shared__ float sA[2][3];
    int nbr[3];
    nbr[0] = l > 0 ? l - 1 : 0;
    nbr[1] = l;
    nbr[2] = l < L_ - 1 ? l + 1 : L_ - 1;
    int h = wid / 3, k = wid % 3;
    const float* q  = g_Q  + l * D_ + h * 150;
    const float* kk = g_Km + nbr[k] * D_ + h * 150;
    float a = 0.f;
    for (int j = lane; j < 150; j += 32) a += q[j] * kk[j];
    a = wred(a);
    if (lane == 0) sS[h][k] = a * rsqrtf(150.f);
    __syncthreads();
    if (tid < 2) {
        float m = fmaxf(sS[tid][0], fmaxf(sS[tid][1], sS[tid][2]));
        float e0 = expf(sS[tid][0] - m), e1 = expf(sS[tid][1] - m), e2 = expf(sS[tid][2] - m);
        float s = e0 + e1 + e2;
        sA[tid][0] = e0 / s; sA[tid][1] = e1 / s; sA[tid][2] = e2 / s;
    }
    __syncthreads();
    for (int j = tid; j < D_; j += 192) {
        int hh = j / 150;
        float acc = 0.f;
#pragma unroll
        for (int kx = 0; kx < 3; kx++) acc += sA[hh][kx] * g_Vm[nbr[kx] * D_ + j];
        g_attout[l * D_ + j] = acc;
    }
}

// ---------------- copy rel -> feat[:,300:600], compute norms ---------------
__global__ void postrel_kernel()
{
    int l = blockIdx.x;
    int tid = threadIdx.x;        // 256
    __shared__ float red[8];
    float p = 0.f;
    for (int j = tid; j < D_; j += 256) {
        float v = g_rel[l * D_ + j];
        g_feat[l * 3 * D_ + D_ + j] = v;
        p += v * v;
    }
    p = wred(p);
    if ((tid & 31) == 0) red[tid >> 5] = p;
    __syncthreads();
    if (tid == 0) {
        float s = 0.f;
        for (int i = 0; i < 8; i++) s += red[i];
        g_norm[l] = sqrtf(s);
    }
}

// ---------------- concept attention: one block per (g,l,s) -----------------
__global__ void concept_kernel(const int* __restrict__ src_ids, const int* __restrict__ dst_ids,
                               const float* __restrict__ wgt, const float* __restrict__ sen,
                               const float* __restrict__ table, const float* __restrict__ rvecs)
{
    int u = blockIdx.x;                 // = (g*L + l)*S + s
    int s = u % S_;
    int l = (u / S_) % L_;
    int g = u / (S_ * L_);
    int tid = threadIdx.x;              // 256 threads, 8 warps
    int lane = tid & 31, wid = tid >> 5;

    __shared__ float d[K_][D_];
    __shared__ float ssrc[D_];
    __shared__ float srp[D_];
    __shared__ float du[K_], dsr[K_], dn[K_], beta[K_];
    __shared__ float swk[K_], sse[K_];
    __shared__ int   dmask[K_];
    __shared__ int   sdid[K_];
    __shared__ float red[8];

    int base = u * K_;
    if (tid < K_) {
        int id = dst_ids[base + tid];
        dmask[tid] = (id >= 0);
        sdid[tid]  = id >= 0 ? id : 0;
        swk[tid] = wgt[base + tid];
        sse[tid] = fabsf(sen[base + tid]);
    }
    int sid = src_ids[u];
    int smask = (sid >= 0);
    if (sid < 0) sid = 0;
    __syncthreads();

    const float* rv = rvecs + g * D_;
    // gather 16 dst rows (each warp does 2 rows)
    for (int r = wid; r < K_; r += 8) {
        const float* p = table + (size_t)sdid[r] * D_;
        for (int j = lane; j < D_; j += 32) d[r][j] = p[j];
    }
    // src row + src*r
    {
        const float* p = table + (size_t)sid * D_;
        for (int j = tid; j < D_; j += 256) {
            float v = p[j];
            ssrc[j] = v;
            srp[j]  = v * rv[j];
        }
    }
    __syncthreads();

    const float* uvec = g_rel + l * D_;
    for (int k = wid; k < K_; k += 8) {
        float a = 0.f, b = 0.f, c = 0.f;
        for (int j = lane; j < D_; j += 32) {
            float dv = d[k][j];
            a += uvec[j] * dv;
            b += srp[j] * dv;
            c += dv * dv;
        }
        a = wred(a); b = wred(b); c = wred(c);
        if (lane == 0) { du[k] = a; dsr[k] = b; dn[k] = c; }
    }
    __syncthreads();

    if (tid == 0) {
        float unorm = g_norm[l];
        float vals[K_], a1[K_];
        float mx = -1e30f;
        for (int k = 0; k < K_; k++) {
            float cosv = fabsf(du[k]) / (unorm * sqrtf(dn[k]) + 1e-8f);
            float om = 0.5f * swk[k] * cosv + 0.5f * sse[k];
            vals[k] = dmask[k] ? om : NEG_;
            mx = fmaxf(mx, vals[k]);
        }
        float sum = 0.f;
        for (int k = 0; k < K_; k++) { float e = expf(vals[k] - mx); vals[k] = e; sum += e; }
        for (int k = 0; k < K_; k++) a1[k] = dmask[k] ? vals[k] / sum : 0.f;
        mx = -1e30f;
        for (int k = 0; k < K_; k++) {
            float sv = a1[k] * dsr[k];
            vals[k] = dmask[k] ? sv : NEG_;
            mx = fmaxf(mx, vals[k]);
        }
        sum = 0.f;
        for (int k = 0; k < K_; k++) { float e = expf(vals[k] - mx); vals[k] = e; sum += e; }
        for (int k = 0; k < K_; k++) beta[k] = a1[k] * (dmask[k] ? vals[k] / sum : 0.f);
    }
    __syncthreads();

    int node = l * (3 * S_) + g * S_ + s;
    float part = 0.f;
    for (int j = tid; j < D_; j += 256) {
        float acc = 0.f;
#pragma unroll
        for (int k = 0; k < K_; k++) acc += beta[k] * d[k][j];
        float v = ssrc[j] + rv[j] * acc;
        g_nodes[(size_t)node * D_ + j] = v;
        part += v * uvec[j];
    }
    part = wred(part);
    if (lane == 0) red[wid] = part;
    __syncthreads();
    if (tid == 0) {
        float t = 0.f;
        for (int i = 0; i < 8; i++) t += red[i];
        g_scoreb[node] = t;
        g_nmask[node]  = smask;
    }
}

// ---------------- node attention -> sym -> feat[:,600:900] -----------------
__global__ void sym_kernel()
{
    int l = blockIdx.x;
    int tid = threadIdx.x;        // 256
    __shared__ float att[3 * S_];
    if (tid < 3 * S_)
        att[tid] = g_nmask[l * 3 * S_ + tid] ? g_scoreb[l * 3 * S_ + tid] : NEG_;
    __syncthreads();
    if (tid == 0) {
        float mx = -1e30f;
        for (int n = 0; n < 3 * S_; n++) mx = fmaxf(mx, att[n]);
        float sum = 0.f;
        for (int n = 0; n < 3 * S_; n++) { float e = expf(att[n] - mx); att[n] = e; sum += e; }
        for (int n = 0; n < 3 * S_; n++)
            att[n] = g_nmask[l * 3 * S_ + n] ? att[n] / sum : 0.f;
    }
    __syncthreads();
    for (int j = tid; j < D_; j += 256) {
        float a = 0.f;
        for (int n = 0; n < 3 * S_; n++)
            a += att[n] * g_nodes[(size_t)(l * 3 * S_ + n) * D_ + j];
        g_feat[l * 3 * D_ + 2 * D_ + j] = a;
    }
}

// ---------------- final head: logits + log_softmax -------------------------
__global__ void out_kernel(const float* __restrict__ W_out, const float* __restrict__ b_out,
                           float* __restrict__ out)
{
    int l = blockIdx.x;
    int tid = threadIdx.x;        // 224 threads, 7 warps
    int wid = tid >> 5, lane = tid & 31;
    __shared__ float logit[C_];
    __shared__ float s2[2];
    float a = 0.f;
    for (int j = lane; j < D_; j += 32) a += g_h1[l * D_ + j] * W_out[j * C_ + wid];
    a = wred(a);
    if (lane == 0) logit[wid] = a + b_out[wid];
    __syncthreads();
    if (tid == 0) {
        float mx = -1e30f;
        for (int c = 0; c < C_; c++) mx = fmaxf(mx, logit[c]);
        float sum = 0.f;
        for (int c = 0; c < C_; c++) sum += expf(logit[c] - mx);
        s2[0] = mx; s2[1] = logf(sum);
    }
    __syncthreads();
    if (tid < C_) out[l * C_ + tid] = logit[tid] - s2[0] - s2[1];
}

// ---------------------------------------------------------------------------
extern "C" void kernel_launch(void* const* d_in, const int* in_sizes, int n_in,
                              void* d_out, int out_size)
{
    const float* utt      = (const float*)d_in[0];
    const int*   str_src  = (const int*)d_in[1];
    const int*   str_dst  = (const int*)d_in[2];
    const int*   str_typ  = (const int*)d_in[3];
    const int*   cpt_src  = (const int*)d_in[4];
    const int*   cpt_dst  = (const int*)d_in[5];
    const float* cpt_w    = (const float*)d_in[6];
    const float* cpt_sen  = (const float*)d_in[7];
    const float* table    = (const float*)d_in[8];
    const float* W_basis  = (const float*)d_in[9];
    const float* comp     = (const float*)d_in[10];
    const float* W_self   = (const float*)d_in[11];
    const float* b_rgcn   = (const float*)d_in[12];
    const float* Wq       = (const float*)d_in[13];
    const float* Wk       = (const float*)d_in[14];
    const float* Wv       = (const float*)d_in[15];
    const float* Wo       = (const float*)d_in[16];
    const float* r_vecs   = (const float*)d_in[17];
    const float* W_fuse   = (const float*)d_in[18];
    const float* b_fuse   = (const float*)d_in[19];
    const float* W_out    = (const float*)d_in[20];
    const float* b_out    = (const float*)d_in[21];
    float* out = (float*)d_out;

    float *Y0, *Y1, *Qb, *Kb, *Vb, *xws, *attout, *rel, *feat, *h1;
    cudaGetSymbolAddress((void**)&Y0, g_Y0);
    cudaGetSymbolAddress((void**)&Y1, g_Y1);
    cudaGetSymbolAddress((void**)&Qb, g_Q);
    cudaGetSymbolAddress((void**)&Kb, g_Km);
    cudaGetSymbolAddress((void**)&Vb, g_Vm);
    cudaGetSymbolAddress((void**)&xws, g_xws);
    cudaGetSymbolAddress((void**)&attout, g_attout);
    cudaGetSymbolAddress((void**)&rel, g_rel);
    cudaGetSymbolAddress((void**)&feat, g_feat);
    cudaGetSymbolAddress((void**)&h1, g_h1);

    dim3 gg((D_ + 31) / 32, (L_ + 31) / 32);
    gemm_kernel<<<gg, 256>>>(utt, W_basis,           nullptr, Y0,  L_, D_, D_, D_, 0);
    gemm_kernel<<<gg, 256>>>(utt, W_basis + D_ * D_, nullptr, Y1,  L_, D_, D_, D_, 0);
    gemm_kernel<<<gg, 256>>>(utt, Wq,                nullptr, Qb,  L_, D_, D_, D_, 0);
    gemm_kernel<<<gg, 256>>>(utt, Wk,                nullptr, Kb,  L_, D_, D_, D_, 0);
    gemm_kernel<<<gg, 256>>>(utt, Wv,                nullptr, Vb,  L_, D_, D_, D_, 0);
    gemm_kernel<<<gg, 256>>>(utt, W_self,            b_rgcn,  xws, L_, D_, D_, D_, 0);

    rgcn_kernel<<<L_, 320>>>(str_src, str_dst, str_typ, comp);
    relatt_kernel<<<L_, 192>>>();
    gemm_kernel<<<gg, 256>>>(attout, Wo, nullptr, rel, L_, D_, D_, D_, 0);
    postrel_kernel<<<L_, 256>>>();

    concept_kernel<<<3 * L_ * S_, 256>>>(cpt_src, cpt_dst, cpt_w, cpt_sen, table, r_vecs);
    sym_kernel<<<L_, 256>>>();

    gemm_kernel<<<gg, 256>>>(feat, W_fuse, b_fuse, h1, L_, D_, 3 * D_, D_, 1);
    out_kernel<<<L_, 224>>>(W_out, b_out, out);
}

// round 2
// speedup vs baseline: 1.3493x; 1.3493x over previous
#include <cuda_runtime.h>
#include <cuda_bf16.h>
#include <math.h>

#define L_ 256
#define D_ 300
#define S_ 16
#define K_ 16
#define E_ 2048
#define C_ 7
#define NEG_ (-1000000000.0f)
#define D4_ 75          // D_/4 float4 per row

// ---------------- scratch ---------------------------------------------------
__device__ float g_Y0[L_ * D_];
__device__ float g_Y1[L_ * D_];
__device__ float g_Q[L_ * D_];
__device__ float g_Km[L_ * D_];
__device__ float g_Vm[L_ * D_];
__device__ float g_xws[L_ * D_];
__device__ float g_attout[L_ * D_];
__device__ float g_rel[L_ * D_];
__device__ float g_feat[L_ * 3 * D_];
__device__ float g_nodes[L_ * 3 * S_ * D_];
__device__ float g_scoreb[L_ * 3 * S_];
__device__ int   g_nmask[L_ * 3 * S_];
__device__ float g_h1[L_ * D_];

__device__ __forceinline__ float wred(float v) {
#pragma unroll
    for (int o = 16; o; o >>= 1) v += __shfl_xor_sync(0xFFFFFFFFu, v, o);
    return v;
}
__device__ __forceinline__ float dot4(float4 a, float4 b) {
    return a.x * b.x + a.y * b.y + a.z * b.z + a.w * b.w;
}

// ---------------- double-buffered 32x32 GEMM core ---------------------------
__device__ __forceinline__ void gemm_core(
    const float* __restrict__ A, const float* __restrict__ B,
    const float* __restrict__ bias, float* __restrict__ C, float* __restrict__ C2,
    int M, int N, int K, int ldc, int ldc2, int relu,
    float (*As)[32][33], float (*Bs)[32][33])
{
    int tx = threadIdx.x & 31;
    int ty = threadIdx.x >> 5;
    int row0 = blockIdx.y * 32;
    int col  = blockIdx.x * 32 + tx;
    float acc[4] = {0.f, 0.f, 0.f, 0.f};
    int T = (K + 31) >> 5;

    // preload tile 0
#pragma unroll
    for (int i = 0; i < 4; i++) {
        int r = ty + 8 * i;
        int ar = row0 + r;
        As[0][r][tx] = (ar < M && tx < K) ? A[ar * K + tx] : 0.f;
        Bs[0][r][tx] = (r < K && col < N) ? B[r * N + col] : 0.f;
    }
    __syncthreads();

    for (int t = 0; t < T; t++) {
        float ap[4], bp[4];
        int k0n = (t + 1) << 5;
        bool more = (t + 1 < T);
        if (more) {
#pragma unroll
            for (int i = 0; i < 4; i++) {
                int r = ty + 8 * i;
                int ar = row0 + r, ac = k0n + tx;
                ap[i] = (ar < M && ac < K) ? A[ar * K + ac] : 0.f;
                int br = k0n + r;
                bp[i] = (br < K && col < N) ? B[br * N + col] : 0.f;
            }
        }
        int b = t & 1;
#pragma unroll
        for (int kk = 0; kk < 32; kk++) {
            float bv = Bs[b][kk][tx];
#pragma unroll
            for (int i = 0; i < 4; i++) acc[i] += As[b][ty + 8 * i][kk] * bv;
        }
        if (more) {
            int nb = b ^ 1;
#pragma unroll
            for (int i = 0; i < 4; i++) {
                int r = ty + 8 * i;
                As[nb][r][tx] = ap[i];
                Bs[nb][r][tx] = bp[i];
            }
        }
        __syncthreads();
    }

    if (col < N) {
        float bv = bias ? bias[col] : 0.f;
#pragma unroll
        for (int i = 0; i < 4; i++) {
            int r = row0 + ty + 8 * i;
            if (r < M) {
                float v = acc[i] + bv;
                if (relu) v = fmaxf(v, 0.f);
                C[r * ldc + col] = v;
                if (C2) C2[r * ldc2 + col] = v;
            }
        }
    }
}

struct Batch6 {
    const float* B[6];
    const float* bias[6];
    float* C[6];
};

__global__ void gemm6_kernel(const float* __restrict__ A, Batch6 p)
{
    __shared__ float As[2][32][33];
    __shared__ float Bs[2][32][33];
    int z = blockIdx.z;
    gemm_core(A, p.B[z], p.bias[z], p.C[z], nullptr,
              L_, D_, D_, D_, 0, 0, As, Bs);
}

__global__ void gemm_kernel(const float* __restrict__ A, const float* __restrict__ B,
                            const float* __restrict__ bias, float* __restrict__ C,
                            float* __restrict__ C2,
                            int M, int N, int K, int ldc, int ldc2, int relu)
{
    __shared__ float As[2][32][33];
    __shared__ float Bs[2][32][33];
    gemm_core(A, B, bias, C, C2, M, N, K, ldc, ldc2, relu, As, Bs);
}

// ---------------- RGCN + windowed attention in one launch -------------------
__global__ void combo_kernel(const int* __restrict__ esrc, const int* __restrict__ edst,
                             const int* __restrict__ etyp, const float* __restrict__ comp)
{
    int tid = threadIdx.x;          // 320 threads
    if (blockIdx.x < L_) {
        // -------- RGCN: feat[:,0:300] = xws + segment_sum --------
        int l = blockIdx.x;
        __shared__ int s_src[256], s_dst[256], s_typ[256];
        float acc = 0.f;
        for (int base = 0; base < E_; base += 256) {
            if (tid < 256) {
                s_src[tid] = esrc[base + tid];
                s_dst[tid] = edst[base + tid];
                s_typ[tid] = etyp[base + tid];
            }
            __syncthreads();
            if (tid < D_) {
                for (int e = 0; e < 256; e++) {
                    if (s_dst[e] == l) {
                        int s = s_src[e], t = s_typ[e];
                        acc += comp[t * 2] * g_Y0[s * D_ + tid]
                             + comp[t * 2 + 1] * g_Y1[s * D_ + tid];
                    }
                }
            }
            __syncthreads();
        }
        if (tid < D_) g_feat[l * 3 * D_ + tid] = g_xws[l * D_ + tid] + acc;
    } else {
        // -------- windowed attention (center query only) --------
        int l = blockIdx.x - L_;
        int wid = tid >> 5, lane = tid & 31;
        __shared__ float sS[2][3];
        __shared__ float sA[2][3];
        int nbr[3];
        nbr[0] = l > 0 ? l - 1 : 0;
        nbr[1] = l;
        nbr[2] = l < L_ - 1 ? l + 1 : L_ - 1;
        if (wid < 6) {
            int h = wid / 3, k = wid % 3;
            const float* q  = g_Q  + l * D_ + h * 150;
            const float* kk = g_Km + nbr[k] * D_ + h * 150;
            float a = 0.f;
            for (int j = lane; j < 150; j += 32) a += q[j] * kk[j];
            a = wred(a);
            if (lane == 0) sS[h][k] = a * rsqrtf(150.f);
        }
        __syncthreads();
        if (tid < 2) {
            float m = fmaxf(sS[tid][0], fmaxf(sS[tid][1], sS[tid][2]));
            float e0 = expf(sS[tid][0] - m), e1 = expf(sS[tid][1] - m), e2 = expf(sS[tid][2] - m);
            float s = e0 + e1 + e2;
            sA[tid][0] = e0 / s; sA[tid][1] = e1 / s; sA[tid][2] = e2 / s;
        }
        __syncthreads();
        for (int j = tid; j < D_; j += 320) {
            int hh = j / 150;
            float acc = 0.f;
#pragma unroll
            for (int kx = 0; kx < 3; kx++) acc += sA[hh][kx] * g_Vm[nbr[kx] * D_ + j];
            g_attout[l * D_ + j] = acc;
        }
    }
}

// ---------------- concept attention: one block per (g,l,s) ------------------
__global__ void concept_kernel(const int* __restrict__ src_ids, const int* __restrict__ dst_ids,
                               const float* __restrict__ wgt, const float* __restrict__ sen,
                               const float* __restrict__ table, const float* __restrict__ rvecs)
{
    int u = blockIdx.x;                 // (g*L + l)*S + s
    int s = u % S_;
    int l = (u / S_) % L_;
    int g = u / (S_ * L_);
    int tid = threadIdx.x;              // 256 threads, 8 warps
    int lane = tid & 31, wid = tid >> 5;

    __shared__ float4 sd4[K_][D4_];
    __shared__ float4 su4[D4_];
    __shared__ float4 ssrc4[D4_];
    __shared__ float4 srp4[D4_];
    __shared__ float  upart[D4_ + 1];
    __shared__ float du[K_], dsr[K_], dn[K_], beta[K_];
    __shared__ float swk[K_], sse[K_];
    __shared__ int   dmask[K_], sdid[K_];
    __shared__ float red[8];
    __shared__ float s_unorm;

    int base = u * K_;
    if (tid < K_) {
        int id = dst_ids[base + tid];
        dmask[tid] = (id >= 0);
        sdid[tid]  = id >= 0 ? id : 0;
        swk[tid] = wgt[base + tid];
        sse[tid] = fabsf(sen[base + tid]);
    }
    int sid = src_ids[u];               // uniform broadcast load
    int smask = (sid >= 0);
    if (sid < 0) sid = 0;
    __syncthreads();

    // phase A: src row, src*r, u vector, partial |u|^2
    const float4* rv4p = (const float4*)(rvecs + g * D_);
    if (tid < D4_) {
        float4 sv = ((const float4*)(table + (size_t)sid * D_))[tid];
        float4 rv = rv4p[tid];
        ssrc4[tid] = sv;
        srp4[tid]  = make_float4(sv.x * rv.x, sv.y * rv.y, sv.z * rv.z, sv.w * rv.w);
        float4 uu = ((const float4*)(g_rel + l * D_))[tid];
        su4[tid] = uu;
        upart[tid] = uu.x * uu.x + uu.y * uu.y + uu.z * uu.z + uu.w * uu.w;
    }

    // phase B: each warp gathers 2 dst rows (float4), stores to smem
    int r0 = wid * 2, r1 = r0 + 1;
    const float4* d0 = (const float4*)(table + (size_t)sdid[r0] * D_);
    const float4* d1 = (const float4*)(table + (size_t)sdid[r1] * D_);
    bool g3 = (lane + 64) < D4_;
    float4 z4 = make_float4(0.f, 0.f, 0.f, 0.f);
    float4 v0a = d0[lane],     v1a = d1[lane];
    float4 v0b = d0[lane + 32], v1b = d1[lane + 32];
    float4 v0c = g3 ? d0[lane + 64] : z4;
    float4 v1c = g3 ? d1[lane + 64] : z4;
    sd4[r0][lane] = v0a;  sd4[r0][lane + 32] = v0b;  if (g3) sd4[r0][lane + 64] = v0c;
    sd4[r1][lane] = v1a;  sd4[r1][lane + 32] = v1b;  if (g3) sd4[r1][lane + 64] = v1c;
    __syncthreads();

    // dots against u and src*r, plus |d|^2
    {
        float4 ua = su4[lane], ub = su4[lane + 32], uc = g3 ? su4[lane + 64] : z4;
        float4 pa = srp4[lane], pb = srp4[lane + 32], pc = g3 ? srp4[lane + 64] : z4;
        float a0 = dot4(ua, v0a) + dot4(ub, v0b) + dot4(uc, v0c);
        float b0 = dot4(pa, v0a) + dot4(pb, v0b) + dot4(pc, v0c);
        float c0 = dot4(v0a, v0a) + dot4(v0b, v0b) + dot4(v0c, v0c);
        float a1 = dot4(ua, v1a) + dot4(ub, v1b) + dot4(uc, v1c);
        float b1 = dot4(pa, v1a) + dot4(pb, v1b) + dot4(pc, v1c);
        float c1 = dot4(v1a, v1a) + dot4(v1b, v1b) + dot4(v1c, v1c);
        a0 = wred(a0); b0 = wred(b0); c0 = wred(c0);
        a1 = wred(a1); b1 = wred(b1); c1 = wred(c1);
        if (lane == 0) {
            du[r0] = a0; dsr[r0] = b0; dn[r0] = c0;
            du[r1] = a1; dsr[r1] = b1; dn[r1] = c1;
        }
    }
    if (wid == 0) {   // |u| norm
        float p = upart[lane] + upart[lane + 32] + (g3 ? upart[lane + 64] : 0.f);
        p = wred(p);
        if (lane == 0) s_unorm = sqrtf(p);
    }
    __syncthreads();

    // phase C: 16-lane softmax chain -> beta = alpha1*alpha2
    if (wid == 0) {
        int k = lane & 15;
        float unorm = s_unorm;
        float cosv = fabsf(du[k]) / (unorm * sqrtf(dn[k]) + 1e-8f);
        float om = 0.5f * swk[k] * cosv + 0.5f * sse[k];
        float v = dmask[k] ? om : NEG_;
        float m = v;
#pragma unroll
        for (int o = 8; o; o >>= 1) m = fmaxf(m, __shfl_xor_sync(0xFFFFFFFFu, m, o));
        float e = expf(v - m);
        float sm = e;
#pragma unroll
        for (int o = 8; o; o >>= 1) sm += __shfl_xor_sync(0xFFFFFFFFu, sm, o);
        float a1v = dmask[k] ? e / sm : 0.f;

        float sv = a1v * dsr[k];
        v = dmask[k] ? sv : NEG_;
        m = v;
#pragma unroll
        for (int o = 8; o; o >>= 1) m = fmaxf(m, __shfl_xor_sync(0xFFFFFFFFu, m, o));
        e = expf(v - m);
        sm = e;
#pragma unroll
        for (int o = 8; o; o >>= 1) sm += __shfl_xor_sync(0xFFFFFFFFu, sm, o);
        float b2 = a1v * (dmask[k] ? e / sm : 0.f);
        if (lane < 16) beta[k] = b2;
    }
    __syncthreads();

    // phase D: node vector + score
    const float* sdf = (const float*)sd4;
    const float* uf  = (const float*)su4;
    const float* sf  = (const float*)ssrc4;
    const float* rvf = (const float*)rv4p;
    int node = l * (3 * S_) + g * S_ + s;
    float part = 0.f;
    for (int j = tid; j < D_; j += 256) {
        float acc = 0.f;
#pragma unroll
        for (int k = 0; k < K_; k++) acc += beta[k] * sdf[k * D_ + j];
        float v = sf[j] + rvf[j] * acc;
        g_nodes[(size_t)node * D_ + j] = v;
        part += v * uf[j];
    }
    part = wred(part);
    if (lane == 0) red[wid] = part;
    __syncthreads();
    if (tid == 0) {
        float t = 0.f;
        for (int i = 0; i < 8; i++) t += red[i];
        g_scoreb[node] = t;
        g_nmask[node]  = smask;
    }
}

// ---------------- node attention -> sym -> feat[:,600:900] ------------------
__global__ void sym_kernel()
{
    int l = blockIdx.x;
    int tid = threadIdx.x;        // 256
    __shared__ float att[3 * S_];
    if (tid < 3 * S_)
        att[tid] = g_nmask[l * 3 * S_ + tid] ? g_scoreb[l * 3 * S_ + tid] : NEG_;
    __syncthreads();
    if (tid == 0) {
        float mx = -1e30f;
        for (int n = 0; n < 3 * S_; n++) mx = fmaxf(mx, att[n]);
        float sum = 0.f;
        for (int n = 0; n < 3 * S_; n++) { float e = expf(att[n] - mx); att[n] = e; sum += e; }
        for (int n = 0; n < 3 * S_; n++)
            att[n] = g_nmask[l * 3 * S_ + n] ? att[n] / sum : 0.f;
    }
    __syncthreads();
    for (int j = tid; j < D_; j += 256) {
        float a = 0.f;
        for (int n = 0; n < 3 * S_; n++)
            a += att[n] * g_nodes[(size_t)(l * 3 * S_ + n) * D_ + j];
        g_feat[l * 3 * D_ + 2 * D_ + j] = a;
    }
}

// ---------------- final head: logits + log_softmax --------------------------
__global__ void out_kernel(const float* __restrict__ W_out, const float* __restrict__ b_out,
                           float* __restrict__ out)
{
    int l = blockIdx.x;
    int tid = threadIdx.x;        // 224 threads, 7 warps
    int wid = tid >> 5, lane = tid & 31;
    __shared__ float logit[C_];
    __shared__ float s2[2];
    float a = 0.f;
    for (int j = lane; j < D_; j += 32) a += g_h1[l * D_ + j] * W_out[j * C_ + wid];
    a = wred(a);
    if (lane == 0) logit[wid] = a + b_out[wid];
    __syncthreads();
    if (tid == 0) {
        float mx = -1e30f;
        for (int c = 0; c < C_; c++) mx = fmaxf(mx, logit[c]);
        float sum = 0.f;
        for (int c = 0; c < C_; c++) sum += expf(logit[c] - mx);
        s2[0] = mx; s2[1] = logf(sum);
    }
    __syncthreads();
    if (tid < C_) out[l * C_ + tid] = logit[tid] - s2[0] - s2[1];
}

// ---------------------------------------------------------------------------
extern "C" void kernel_launch(void* const* d_in, const int* in_sizes, int n_in,
                              void* d_out, int out_size)
{
    const float* utt      = (const float*)d_in[0];
    const int*   str_src  = (const int*)d_in[1];
    const int*   str_dst  = (const int*)d_in[2];
    const int*   str_typ  = (const int*)d_in[3];
    const int*   cpt_src  = (const int*)d_in[4];
    const int*   cpt_dst  = (const int*)d_in[5];
    const float* cpt_w    = (const float*)d_in[6];
    const float* cpt_sen  = (const float*)d_in[7];
    const float* table    = (const float*)d_in[8];
    const float* W_basis  = (const float*)d_in[9];
    const float* comp     = (const float*)d_in[10];
    const float* W_self   = (const float*)d_in[11];
    const float* b_rgcn   = (const float*)d_in[12];
    const float* Wq       = (const float*)d_in[13];
    const float* Wk       = (const float*)d_in[14];
    const float* Wv       = (const float*)d_in[15];
    const float* Wo       = (const float*)d_in[16];
    const float* r_vecs   = (const float*)d_in[17];
    const float* W_fuse   = (const float*)d_in[18];
    const float* b_fuse   = (const float*)d_in[19];
    const float* W_out    = (const float*)d_in[20];
    const float* b_out    = (const float*)d_in[21];
    float* out = (float*)d_out;

    float *Y0, *Y1, *Qb, *Kb, *Vb, *xws, *attout, *rel, *feat, *h1;
    cudaGetSymbolAddress((void**)&Y0, g_Y0);
    cudaGetSymbolAddress((void**)&Y1, g_Y1);
    cudaGetSymbolAddress((void**)&Qb, g_Q);
    cudaGetSymbolAddress((void**)&Kb, g_Km);
    cudaGetSymbolAddress((void**)&Vb, g_Vm);
    cudaGetSymbolAddress((void**)&xws, g_xws);
    cudaGetSymbolAddress((void**)&attout, g_attout);
    cudaGetSymbolAddress((void**)&rel, g_rel);
    cudaGetSymbolAddress((void**)&feat, g_feat);
    cudaGetSymbolAddress((void**)&h1, g_h1);

    Batch6 p;
    p.B[0] = W_basis;            p.bias[0] = nullptr; p.C[0] = Y0;
    p.B[1] = W_basis + D_ * D_;  p.bias[1] = nullptr; p.C[1] = Y1;
    p.B[2] = Wq;                 p.bias[2] = nullptr; p.C[2] = Qb;
    p.B[3] = Wk;                 p.bias[3] = nullptr; p.C[3] = Kb;
    p.B[4] = Wv;                 p.bias[4] = nullptr; p.C[4] = Vb;
    p.B[5] = W_self;             p.bias[5] = b_rgcn;  p.C[5] = xws;

    dim3 g6((D_ + 31) / 32, (L_ + 31) / 32, 6);
    gemm6_kernel<<<g6, 256>>>(utt, p);

    combo_kernel<<<2 * L_, 320>>>(str_src, str_dst, str_typ, comp);

    dim3 gg((D_ + 31) / 32, (L_ + 31) / 32);
    // rel = attout @ Wo, also written into feat[:,300:600]
    gemm_kernel<<<gg, 256>>>(attout, Wo, nullptr, rel, feat + D_, L_, D_, D_, D_, 3 * D_, 0);

    concept_kernel<<<3 * L_ * S_, 256>>>(cpt_src, cpt_dst, cpt_w, cpt_sen, table, r_vecs);
    sym_kernel<<<L_, 256>>>();

    gemm_kernel<<<gg, 256>>>(feat, W_fuse, b_fuse, h1, nullptr, L_, D_, 3 * D_, D_, 0, 1);
    out_kernel<<<L_, 224>>>(W_out, b_out, out);
}

// round 3
// speedup vs baseline: 1.3982x; 1.0362x over previous
#include <cuda_runtime.h>
#include <cuda_bf16.h>
#include <math.h>

#define L_ 256
#define D_ 300
#define S_ 16
#define K_ 16
#define E_ 2048
#define C_ 7
#define NEG_ (-1000000000.0f)
#define D4_ 75          // D_/4 float4 per row

// ---------------- scratch ---------------------------------------------------
__device__ float g_Y0[L_ * D_];
__device__ float g_Y1[L_ * D_];
__device__ float g_Q[L_ * D_];
__device__ float g_Km[L_ * D_];
__device__ float g_Vm[L_ * D_];
__device__ float g_xws[L_ * D_];
__device__ float g_attout[L_ * D_];
__device__ float g_rel[L_ * D_];
__device__ float g_feat[L_ * 3 * D_];
__device__ float g_nodes[L_ * 3 * S_ * D_];
__device__ float g_scoreb[L_ * 3 * S_];
__device__ int   g_nmask[L_ * 3 * S_];
__device__ float g_h1[L_ * D_];

__device__ __forceinline__ float wred(float v) {
#pragma unroll
    for (int o = 16; o; o >>= 1) v += __shfl_xor_sync(0xFFFFFFFFu, v, o);
    return v;
}
__device__ __forceinline__ float dot4(float4 a, float4 b) {
    return a.x * b.x + a.y * b.y + a.z * b.z + a.w * b.w;
}
__device__ __forceinline__ float4 fma4(float s, float4 a, float4 b) {
    return make_float4(fmaf(s, a.x, b.x), fmaf(s, a.y, b.y),
                       fmaf(s, a.z, b.z), fmaf(s, a.w, b.w));
}

// ---------------- double-buffered 32x32 GEMM core ---------------------------
__device__ __forceinline__ void gemm_core(
    const float* __restrict__ A, const float* __restrict__ B,
    const float* __restrict__ bias, float* __restrict__ C, float* __restrict__ C2,
    int M, int N, int K, int ldc, int ldc2, int relu,
    float (*As)[32][33], float (*Bs)[32][33])
{
    int tx = threadIdx.x & 31;
    int ty = threadIdx.x >> 5;
    int row0 = blockIdx.y * 32;
    int col  = blockIdx.x * 32 + tx;
    float acc[4] = {0.f, 0.f, 0.f, 0.f};
    int T = (K + 31) >> 5;

#pragma unroll
    for (int i = 0; i < 4; i++) {
        int r = ty + 8 * i;
        int ar = row0 + r;
        As[0][r][tx] = (ar < M && tx < K) ? A[ar * K + tx] : 0.f;
        Bs[0][r][tx] = (r < K && col < N) ? B[r * N + col] : 0.f;
    }
    __syncthreads();

    for (int t = 0; t < T; t++) {
        float ap[4], bp[4];
        int k0n = (t + 1) << 5;
        bool more = (t + 1 < T);
        if (more) {
#pragma unroll
            for (int i = 0; i < 4; i++) {
                int r = ty + 8 * i;
                int ar = row0 + r, ac = k0n + tx;
                ap[i] = (ar < M && ac < K) ? A[ar * K + ac] : 0.f;
                int br = k0n + r;
                bp[i] = (br < K && col < N) ? B[br * N + col] : 0.f;
            }
        }
        int b = t & 1;
#pragma unroll
        for (int kk = 0; kk < 32; kk++) {
            float bv = Bs[b][kk][tx];
#pragma unroll
            for (int i = 0; i < 4; i++) acc[i] += As[b][ty + 8 * i][kk] * bv;
        }
        if (more) {
            int nb = b ^ 1;
#pragma unroll
            for (int i = 0; i < 4; i++) {
                int r = ty + 8 * i;
                As[nb][r][tx] = ap[i];
                Bs[nb][r][tx] = bp[i];
            }
        }
        __syncthreads();
    }

    if (col < N) {
        float bv = bias ? bias[col] : 0.f;
#pragma unroll
        for (int i = 0; i < 4; i++) {
            int r = row0 + ty + 8 * i;
            if (r < M) {
                float v = acc[i] + bv;
                if (relu) v = fmaxf(v, 0.f);
                C[r * ldc + col] = v;
                if (C2) C2[r * ldc2 + col] = v;
            }
        }
    }
}

struct Batch6 {
    const float* B[6];
    const float* bias[6];
    float* C[6];
};

__global__ void gemm6_kernel(const float* __restrict__ A, Batch6 p)
{
    __shared__ float As[2][32][33];
    __shared__ float Bs[2][32][33];
    int z = blockIdx.z;
    gemm_core(A, p.B[z], p.bias[z], p.C[z], nullptr,
              L_, D_, D_, D_, 0, 0, As, Bs);
}

__global__ void gemm_kernel(const float* __restrict__ A, const float* __restrict__ B,
                            const float* __restrict__ bias, float* __restrict__ C,
                            float* __restrict__ C2,
                            int M, int N, int K, int ldc, int ldc2, int relu)
{
    __shared__ float As[2][32][33];
    __shared__ float Bs[2][32][33];
    gemm_core(A, B, bias, C, C2, M, N, K, ldc, ldc2, relu, As, Bs);
}

// ---------------- RGCN + windowed attention in one launch -------------------
// rgcn: 640 threads, split into two halves each scanning 1024 edges;
// partial sums combined through smem.
__global__ void combo_kernel(const int* __restrict__ esrc, const int* __restrict__ edst,
                             const int* __restrict__ etyp, const float* __restrict__ comp)
{
    int tid = threadIdx.x;          // 640 threads
    if (blockIdx.x < L_) {
        int l = blockIdx.x;
        __shared__ int s_src[E_ / 2], s_dst[E_ / 2], s_typ[E_ / 2];
        __shared__ float scomp[12];
        __shared__ float part[D_];
        if (tid < 12) scomp[tid] = comp[tid];
        int half = tid >= 320;              // which 1024-edge half
        int jt = half ? tid - 320 : tid;    // 0..319
        int ebase = half ? E_ / 2 : 0;

        // stage this half's 1024 edges (each half's 320 threads load its chunk)
        for (int e = jt; e < E_ / 2; e += 320) {
            int idx = half ? e + E_ / 2 : e;
            // store into the half-shared buffers at disjoint... (buffers shared: use
            // one buffer per half) -- allocate full-size split:
            (void)idx;
        }
        // Simpler: both halves share one staging pass over all edges.
        __syncthreads();
        // load edges cooperatively (all 640 threads, full 2048 edges in 2 passes
        // of 1024 staged in the 1024-entry buffers)
        float acc = 0.f;
        for (int pass = 0; pass < 2; pass++) {
            for (int e = tid; e < E_ / 2; e += 640) {
                int ge = pass * (E_ / 2) + e;
                s_src[e] = esrc[ge];
                s_dst[e] = edst[ge];
                s_typ[e] = etyp[ge];
            }
            __syncthreads();
            if (jt < D_) {
                int e0 = half ? E_ / 4 : 0;
                int e1 = half ? E_ / 2 : E_ / 4;
                for (int e = e0; e < e1; e++) {
                    if (s_dst[e] == l) {
                        int s = s_src[e], t = s_typ[e];
                        acc += scomp[t * 2] * g_Y0[s * D_ + jt]
                             + scomp[t * 2 + 1] * g_Y1[s * D_ + jt];
                    }
                }
            }
            __syncthreads();
        }
        // combine halves: half0 writes, half1 adds
        if (!half && jt < D_) part[jt] = acc;
        __syncthreads();
        if (half && jt < D_) part[jt] += acc;
        __syncthreads();
        if (!half && jt < D_)
            g_feat[l * 3 * D_ + jt] = g_xws[l * D_ + jt] + part[jt];
    } else {
        // -------- windowed attention (center query only) --------
        int l = blockIdx.x - L_;
        int wid = tid >> 5, lane = tid & 31;
        __shared__ float sS[2][3];
        __shared__ float sA[2][3];
        int nbr[3];
        nbr[0] = l > 0 ? l - 1 : 0;
        nbr[1] = l;
        nbr[2] = l < L_ - 1 ? l + 1 : L_ - 1;
        if (wid < 6) {
            int h = wid / 3, k = wid % 3;
            const float* q  = g_Q  + l * D_ + h * 150;
            const float* kk = g_Km + nbr[k] * D_ + h * 150;
            float a = 0.f;
            for (int j = lane; j < 150; j += 32) a += q[j] * kk[j];
            a = wred(a);
            if (lane == 0) sS[h][k] = a * rsqrtf(150.f);
        }
        __syncthreads();
        if (tid < 2) {
            float m = fmaxf(sS[tid][0], fmaxf(sS[tid][1], sS[tid][2]));
            float e0 = expf(sS[tid][0] - m), e1 = expf(sS[tid][1] - m), e2 = expf(sS[tid][2] - m);
            float s = e0 + e1 + e2;
            sA[tid][0] = e0 / s; sA[tid][1] = e1 / s; sA[tid][2] = e2 / s;
        }
        __syncthreads();
        for (int j = tid; j < D_; j += 640) {
            int hh = j / 150;
            float acc = 0.f;
#pragma unroll
            for (int kx = 0; kx < 3; kx++) acc += sA[hh][kx] * g_Vm[nbr[kx] * D_ + j];
            g_attout[l * D_ + j] = acc;
        }
    }
}

// ---------------- concept attention: one block per (g,l,s) ------------------
// dst rows live in registers (each warp owns 2 rows); smem only for shared
// vectors + per-warp partial slabs.
__global__ void __launch_bounds__(256, 4)
concept_kernel(const int* __restrict__ src_ids, const int* __restrict__ dst_ids,
               const float* __restrict__ wgt, const float* __restrict__ sen,
               const float* __restrict__ table, const float* __restrict__ rvecs)
{
    int u = blockIdx.x;                 // (g*L + l)*S + s
    int s = u % S_;
    int l = (u / S_) % L_;
    int g = u / (S_ * L_);
    int tid = threadIdx.x;              // 256 threads, 8 warps
    int lane = tid & 31, wid = tid >> 5;

    __shared__ float4 su4[D4_];
    __shared__ float4 srp4[D4_];
    __shared__ float4 ssrc4[D4_];
    __shared__ float4 rv4s[D4_];
    __shared__ float4 part4[8][D4_];
    __shared__ float du[K_], dsr[K_], dn[K_], beta[K_];
    __shared__ float swk[K_], sse[K_];
    __shared__ int   dmask[K_], sdid[K_];
    __shared__ float red[8];
    __shared__ float s_unorm;

    int base = u * K_;
    if (tid < K_) {
        int id = dst_ids[base + tid];
        dmask[tid] = (id >= 0);
        sdid[tid]  = id >= 0 ? id : 0;
        swk[tid] = wgt[base + tid];
        sse[tid] = fabsf(sen[base + tid]);
    }
    int sid = src_ids[u];
    int smask = (sid >= 0);
    if (sid < 0) sid = 0;
    __syncthreads();

    // phase A: shared vectors
    const float4* rv4p = (const float4*)(rvecs + g * D_);
    if (tid < D4_) {
        float4 sv = ((const float4*)(table + (size_t)sid * D_))[tid];
        float4 rv = rv4p[tid];
        ssrc4[tid] = sv;
        rv4s[tid]  = rv;
        srp4[tid]  = make_float4(sv.x * rv.x, sv.y * rv.y, sv.z * rv.z, sv.w * rv.w);
        su4[tid]   = ((const float4*)(g_rel + l * D_))[tid];
    }

    // phase B: each warp gathers its 2 dst rows into registers
    int r0 = wid * 2, r1 = r0 + 1;
    const float4* d0 = (const float4*)(table + (size_t)sdid[r0] * D_);
    const float4* d1 = (const float4*)(table + (size_t)sdid[r1] * D_);
    bool g3 = (lane + 64) < D4_;
    float4 z4 = make_float4(0.f, 0.f, 0.f, 0.f);
    float4 v0a = d0[lane],      v1a = d1[lane];
    float4 v0b = d0[lane + 32], v1b = d1[lane + 32];
    float4 v0c = g3 ? d0[lane + 64] : z4;
    float4 v1c = g3 ? d1[lane + 64] : z4;
    __syncthreads();

    // phase C: dots from registers against smem vectors
    {
        float4 ua = su4[lane], ub = su4[lane + 32], uc = g3 ? su4[lane + 64] : z4;
        float4 pa = srp4[lane], pb = srp4[lane + 32], pc = g3 ? srp4[lane + 64] : z4;
        float a0 = dot4(ua, v0a) + dot4(ub, v0b) + dot4(uc, v0c);
        float b0 = dot4(pa, v0a) + dot4(pb, v0b) + dot4(pc, v0c);
        float c0 = dot4(v0a, v0a) + dot4(v0b, v0b) + dot4(v0c, v0c);
        float a1 = dot4(ua, v1a) + dot4(ub, v1b) + dot4(uc, v1c);
        float b1 = dot4(pa, v1a) + dot4(pb, v1b) + dot4(pc, v1c);
        float c1 = dot4(v1a, v1a) + dot4(v1b, v1b) + dot4(v1c, v1c);
        a0 = wred(a0); b0 = wred(b0); c0 = wred(c0);
        a1 = wred(a1); b1 = wred(b1); c1 = wred(c1);
        if (lane == 0) {
            du[r0] = a0; dsr[r0] = b0; dn[r0] = c0;
            du[r1] = a1; dsr[r1] = b1; dn[r1] = c1;
        }
        if (wid == 0) {     // |u| from smem copy
            float p = dot4(ua, ua) + dot4(ub, ub) + dot4(uc, uc);
            p = wred(p);
            if (lane == 0) s_unorm = sqrtf(p);
        }
    }
    __syncthreads();

    // phase D: 16-lane softmax chain -> beta = alpha1 * alpha2
    if (wid == 0) {
        int k = lane & 15;
        float unorm = s_unorm;
        float cosv = fabsf(du[k]) / (unorm * sqrtf(dn[k]) + 1e-8f);
        float om = 0.5f * swk[k] * cosv + 0.5f * sse[k];
        float v = dmask[k] ? om : NEG_;
        float m = v;
#pragma unroll
        for (int o = 8; o; o >>= 1) m = fmaxf(m, __shfl_xor_sync(0xFFFFFFFFu, m, o));
        float e = expf(v - m);
        float sm = e;
#pragma unroll
        for (int o = 8; o; o >>= 1) sm += __shfl_xor_sync(0xFFFFFFFFu, sm, o);
        float a1v = dmask[k] ? e / sm : 0.f;

        float sv = a1v * dsr[k];
        v = dmask[k] ? sv : NEG_;
        m = v;
#pragma unroll
        for (int o = 8; o; o >>= 1) m = fmaxf(m, __shfl_xor_sync(0xFFFFFFFFu, m, o));
        e = expf(v - m);
        sm = e;
#pragma unroll
        for (int o = 8; o; o >>= 1) sm += __shfl_xor_sync(0xFFFFFFFFu, sm, o);
        float b2 = a1v * (dmask[k] ? e / sm : 0.f);
        if (lane < 16) beta[k] = b2;
    }
    __syncthreads();

    // phase E: per-warp partial = beta[r0]*row0 + beta[r1]*row1 (registers)
    {
        float b0 = beta[r0], b1 = beta[r1];
        float4 pa = fma4(b0, v0a, make_float4(b1 * v1a.x, b1 * v1a.y, b1 * v1a.z, b1 * v1a.w));
        float4 pb = fma4(b0, v0b, make_float4(b1 * v1b.x, b1 * v1b.y, b1 * v1b.z, b1 * v1b.w));
        part4[wid][lane] = pa;
        part4[wid][lane + 32] = pb;
        if (g3) {
            float4 pc = fma4(b0, v0c, make_float4(b1 * v1c.x, b1 * v1c.y, b1 * v1c.z, b1 * v1c.w));
            part4[wid][lane + 64] = pc;
        }
    }
    __syncthreads();

    // phase F: reduce partials, form node row, write + score
    int node = l * (3 * S_) + g * S_ + s;
    float sc = 0.f;
    if (tid < D4_) {
        float4 acc = part4[0][tid];
#pragma unroll
        for (int w = 1; w < 8; w++) {
            float4 p = part4[w][tid];
            acc.x += p.x; acc.y += p.y; acc.z += p.z; acc.w += p.w;
        }
        float4 rv = rv4s[tid], sv = ssrc4[tid];
        float4 v = make_float4(fmaf(rv.x, acc.x, sv.x), fmaf(rv.y, acc.y, sv.y),
                               fmaf(rv.z, acc.z, sv.z), fmaf(rv.w, acc.w, sv.w));
        ((float4*)(g_nodes + (size_t)node * D_))[tid] = v;
        sc = dot4(v, su4[tid]);
    }
    sc = wred(sc);
    if (lane == 0) red[wid] = sc;
    __syncthreads();
    if (tid == 0) {
        float t = red[0] + red[1] + red[2];   // only warps 0-2 hold tid<75
        g_scoreb[node] = t;
        g_nmask[node]  = smask;
    }
}

// ---------------- node attention -> sym -> feat[:,600:900] ------------------
__global__ void sym_kernel()
{
    int l = blockIdx.x;
    int tid = threadIdx.x;        // 256
    __shared__ float att[3 * S_];
    if (tid < 3 * S_)
        att[tid] = g_nmask[l * 3 * S_ + tid] ? g_scoreb[l * 3 * S_ + tid] : NEG_;
    __syncthreads();
    if (tid == 0) {
        float mx = -1e30f;
        for (int n = 0; n < 3 * S_; n++) mx = fmaxf(mx, att[n]);
        float sum = 0.f;
        for (int n = 0; n < 3 * S_; n++) { float e = expf(att[n] - mx); att[n] = e; sum += e; }
        for (int n = 0; n < 3 * S_; n++)
            att[n] = g_nmask[l * 3 * S_ + n] ? att[n] / sum : 0.f;
    }
    __syncthreads();
    if (tid < D4_) {
        float4 a = make_float4(0.f, 0.f, 0.f, 0.f);
        for (int n = 0; n < 3 * S_; n++) {
            float w = att[n];
            float4 v = ((const float4*)(g_nodes + (size_t)(l * 3 * S_ + n) * D_))[tid];
            a.x += w * v.x; a.y += w * v.y; a.z += w * v.z; a.w += w * v.w;
        }
        // feat row offset 2*D_ = 600 floats; 600*4 bytes divisible by 16
        ((float4*)(g_feat + (size_t)l * 3 * D_ + 2 * D_))[tid] = a;
    }
}

// ---------------- final head: logits + log_softmax --------------------------
__global__ void out_kernel(const float* __restrict__ W_out, const float* __restrict__ b_out,
                           float* __restrict__ out)
{
    int l = blockIdx.x;
    int tid = threadIdx.x;        // 224 threads, 7 warps
    int wid = tid >> 5, lane = tid & 31;
    __shared__ float logit[C_];
    __shared__ float s2[2];
    float a = 0.f;
    for (int j = lane; j < D_; j += 32) a += g_h1[l * D_ + j] * W_out[j * C_ + wid];
    a = wred(a);
    if (lane == 0) logit[wid] = a + b_out[wid];
    __syncthreads();
    if (tid == 0) {
        float mx = -1e30f;
        for (int c = 0; c < C_; c++) mx = fmaxf(mx, logit[c]);
        float sum = 0.f;
        for (int c = 0; c < C_; c++) sum += expf(logit[c] - mx);
        s2[0] = mx; s2[1] = logf(sum);
    }
    __syncthreads();
    if (tid < C_) out[l * C_ + tid] = logit[tid] - s2[0] - s2[1];
}

// ---------------------------------------------------------------------------
extern "C" void kernel_launch(void* const* d_in, const int* in_sizes, int n_in,
                              void* d_out, int out_size)
{
    const float* utt      = (const float*)d_in[0];
    const int*   str_src  = (const int*)d_in[1];
    const int*   str_dst  = (const int*)d_in[2];
    const int*   str_typ  = (const int*)d_in[3];
    const int*   cpt_src  = (const int*)d_in[4];
    const int*   cpt_dst  = (const int*)d_in[5];
    const float* cpt_w    = (const float*)d_in[6];
    const float* cpt_sen  = (const float*)d_in[7];
    const float* table    = (const float*)d_in[8];
    const float* W_basis  = (const float*)d_in[9];
    const float* comp     = (const float*)d_in[10];
    const float* W_self   = (const float*)d_in[11];
    const float* b_rgcn   = (const float*)d_in[12];
    const float* Wq       = (const float*)d_in[13];
    const float* Wk       = (const float*)d_in[14];
    const float* Wv       = (const float*)d_in[15];
    const float* Wo       = (const float*)d_in[16];
    const float* r_vecs   = (const float*)d_in[17];
    const float* W_fuse   = (const float*)d_in[18];
    const float* b_fuse   = (const float*)d_in[19];
    const float* W_out    = (const float*)d_in[20];
    const float* b_out    = (const float*)d_in[21];
    float* out = (float*)d_out;

    float *Y0, *Y1, *Qb, *Kb, *Vb, *xws, *attout, *rel, *feat, *h1;
    cudaGetSymbolAddress((void**)&Y0, g_Y0);
    cudaGetSymbolAddress((void**)&Y1, g_Y1);
    cudaGetSymbolAddress((void**)&Qb, g_Q);
    cudaGetSymbolAddress((void**)&Kb, g_Km);
    cudaGetSymbolAddress((void**)&Vb, g_Vm);
    cudaGetSymbolAddress((void**)&xws, g_xws);
    cudaGetSymbolAddress((void**)&attout, g_attout);
    cudaGetSymbolAddress((void**)&rel, g_rel);
    cudaGetSymbolAddress((void**)&feat, g_feat);
    cudaGetSymbolAddress((void**)&h1, g_h1);

    Batch6 p;
    p.B[0] = W_basis;            p.bias[0] = nullptr; p.C[0] = Y0;
    p.B[1] = W_basis + D_ * D_;  p.bias[1] = nullptr; p.C[1] = Y1;
    p.B[2] = Wq;                 p.bias[2] = nullptr; p.C[2] = Qb;
    p.B[3] = Wk;                 p.bias[3] = nullptr; p.C[3] = Kb;
    p.B[4] = Wv;                 p.bias[4] = nullptr; p.C[4] = Vb;
    p.B[5] = W_self;             p.bias[5] = b_rgcn;  p.C[5] = xws;

    dim3 g6((D_ + 31) / 32, (L_ + 31) / 32, 6);
    gemm6_kernel<<<g6, 256>>>(utt, p);

    combo_kernel<<<2 * L_, 640>>>(str_src, str_dst, str_typ, comp);

    dim3 gg((D_ + 31) / 32, (L_ + 31) / 32);
    gemm_kernel<<<gg, 256>>>(attout, Wo, nullptr, rel, feat + D_, L_, D_, D_, D_, 3 * D_, 0);

    concept_kernel<<<3 * L_ * S_, 256>>>(cpt_src, cpt_dst, cpt_w, cpt_sen, table, r_vecs);
    sym_kernel<<<L_, 256>>>();

    gemm_kernel<<<gg, 256>>>(feat, W_fuse, b_fuse, h1, nullptr, L_, D_, 3 * D_, D_, 0, 1);
    out_kernel<<<L_, 224>>>(W_out, b_out, out);
}

// round 6
// speedup vs baseline: 1.6345x; 1.1690x over previous
#include <cuda_runtime.h>
#include <cuda_bf16.h>
#include <cstdint>
#include <math.h>

#define L_ 256
#define D_ 300
#define S_ 16
#define K_ 16
#define E_ 2048
#define C_ 7
#define NEG_ (-1000000000.0f)
#define D4_ 75
#define GST 3            // cp.async pipeline stages

// ---------------- scratch ---------------------------------------------------
__device__ float g_Y0[L_ * D_];
__device__ float g_Y1[L_ * D_];
__device__ float g_Q[L_ * D_];
__device__ float g_Km[L_ * D_];
__device__ float g_Vm[L_ * D_];
__device__ float g_xws[L_ * D_];
__device__ float g_rel[L_ * D_];
__device__ float g_feat[L_ * 3 * D_];
__device__ float g_nodes[L_ * 3 * S_ * D_];
__device__ float g_scoreb[L_ * 3 * S_];
__device__ int   g_nmask[L_ * 3 * S_];
__device__ float g_h1[L_ * D_];

__device__ __forceinline__ float wred(float v) {
#pragma unroll
    for (int o = 16; o; o >>= 1) v += __shfl_xor_sync(0xFFFFFFFFu, v, o);
    return v;
}
__device__ __forceinline__ float dot4(float4 a, float4 b) {
    return a.x * b.x + a.y * b.y + a.z * b.z + a.w * b.w;
}

// ---------------- cp.async helpers ------------------------------------------
// when p is false, src is clamped to a valid address by the caller;
// src-size=0 zero-fills the 16B destination.
__device__ __forceinline__ void cpa16(unsigned int dst, const float* src, bool p) {
    asm volatile("cp.async.cg.shared.global [%0], [%1], 16, %2;"
                 :: "r"(dst), "l"(src), "r"(p ? 16 : 0));
}
__device__ __forceinline__ void cpcommit() {
    asm volatile("cp.async.commit_group;");
}
template<int N>
__device__ __forceinline__ void cpwait() {
    asm volatile("cp.async.wait_group %0;" :: "n"(N));
}

// ---------------- 3-stage cp.async pipelined 32x32 GEMM ---------------------
// C = act(A[MxK] @ B[KxN] + bias). 256 threads.
__device__ __forceinline__ void gemm_core_async(
    const float* __restrict__ A, const float* __restrict__ B,
    const float* __restrict__ bias, float* __restrict__ C,
    int M, int N, int K, int ldc, int relu,
    float (*As)[32][36], float (*Bs)[32][36])
{
    int t  = threadIdx.x;
    int lr = t >> 3;              // 0..31
    int lc = (t & 7) << 2;        // 0,4,...,28
    int tx = t & 31, ty = t >> 5;
    int row0 = blockIdx.y * 32;
    int col0 = blockIdx.x * 32;
    int T = (K + 31) >> 5;

    unsigned int sA = (unsigned int)__cvta_generic_to_shared(&As[0][0][0]);
    unsigned int sB = (unsigned int)__cvta_generic_to_shared(&Bs[0][0][0]);
    const unsigned int stageB = 32 * 36 * 4;
    unsigned int off = (unsigned int)(lr * 36 + lc) * 4;

    float acc[4] = {0.f, 0.f, 0.f, 0.f};

    // prologue
#pragma unroll
    for (int s = 0; s < GST - 1; s++) {
        if (s < T) {
            int k0 = s << 5;
            bool pa = (row0 + lr < M) && (k0 + lc < K);
            const float* pas = pa ? A + (size_t)(row0 + lr) * K + k0 + lc : A;
            cpa16(sA + s * stageB + off, pas, pa);
            bool pb = (k0 + lr < K) && (col0 + lc < N);
            const float* pbs = pb ? B + (size_t)(k0 + lr) * N + col0 + lc : B;
            cpa16(sB + s * stageB + off, pbs, pb);
        }
        cpcommit();
    }

    for (int t0 = 0; t0 < T; t0++) {
        int tl = t0 + GST - 1;
        if (tl < T) {
            int st = tl % GST;
            int k0 = tl << 5;
            bool pa = (row0 + lr < M) && (k0 + lc < K);
            const float* pas = pa ? A + (size_t)(row0 + lr) * K + k0 + lc : A;
            cpa16(sA + st * stageB + off, pas, pa);
            bool pb = (k0 + lr < K) && (col0 + lc < N);
            const float* pbs = pb ? B + (size_t)(k0 + lr) * N + col0 + lc : B;
            cpa16(sB + st * stageB + off, pbs, pb);
        }
        cpcommit();
        cpwait<GST - 2>();
        __syncthreads();
        int st = t0 % GST;
#pragma unroll
        for (int kk = 0; kk < 32; kk++) {
            float bv = Bs[st][kk][tx];
#pragma unroll
            for (int i = 0; i < 4; i++) acc[i] += As[st][ty + 8 * i][kk] * bv;
        }
        __syncthreads();
    }

    int col = col0 + tx;
    if (col < N) {
        float bv = bias ? bias[col] : 0.f;
#pragma unroll
        for (int i = 0; i < 4; i++) {
            int r = row0 + ty + 8 * i;
            if (r < M) {
                float v = acc[i] + bv;
                if (relu) v = fmaxf(v, 0.f);
                C[(size_t)r * ldc + col] = v;
            }
        }
    }
}

struct Batch6 {
    const float* B[6];
    const float* bias[6];
    float* C[6];
};

__global__ void gemm6_kernel(const float* __restrict__ A, Batch6 p)
{
    __shared__ float As[GST][32][36];
    __shared__ float Bs[GST][32][36];
    int z = blockIdx.z;
    gemm_core_async(A, p.B[z], p.bias[z], p.C[z], L_, D_, D_, D_, 0, As, Bs);
}

__global__ void gemm_kernel(const float* __restrict__ A, const float* __restrict__ B,
                            const float* __restrict__ bias, float* __restrict__ C,
                            int M, int N, int K, int ldc, int relu)
{
    __shared__ float As[GST][32][36];
    __shared__ float Bs[GST][32][36];
    gemm_core_async(A, B, bias, C, M, N, K, ldc, relu, As, Bs);
}

// ---------------- RGCN + (windowed attention fused with Wo GEMV) ------------
__global__ void combo_kernel(const int* __restrict__ esrc, const int* __restrict__ edst,
                             const int* __restrict__ etyp, const float* __restrict__ comp,
                             const float* __restrict__ Wo)
{
    int tid = threadIdx.x;          // 640 threads
    if (blockIdx.x < L_) {
        // -------- RGCN: feat[:,0:300] = xws + segment_sum --------
        int l = blockIdx.x;
        __shared__ int s_src[E_ / 2], s_dst[E_ / 2], s_typ[E_ / 2];
        __shared__ float scomp[12];
        __shared__ float part[D_];
        if (tid < 12) scomp[tid] = comp[tid];
        int half = tid >= 320;
        int jt = half ? tid - 320 : tid;
        float acc = 0.f;
        for (int pass = 0; pass < 2; pass++) {
            for (int e = tid; e < E_ / 2; e += 640) {
                int ge = pass * (E_ / 2) + e;
                s_src[e] = esrc[ge];
                s_dst[e] = edst[ge];
                s_typ[e] = etyp[ge];
            }
            __syncthreads();
            if (jt < D_) {
                int e0 = half ? E_ / 4 : 0;
                int e1 = half ? E_ / 2 : E_ / 4;
                for (int e = e0; e < e1; e++) {
                    if (s_dst[e] == l) {
                        int s = s_src[e], ty = s_typ[e];
                        acc += scomp[ty * 2] * g_Y0[s * D_ + jt]
                             + scomp[ty * 2 + 1] * g_Y1[s * D_ + jt];
                    }
                }
            }
            __syncthreads();
        }
        if (!half && jt < D_) part[jt] = acc;
        __syncthreads();
        if (half && jt < D_) part[jt] += acc;
        __syncthreads();
        if (!half && jt < D_)
            g_feat[l * 3 * D_ + jt] = g_xws[l * D_ + jt] + part[jt];
    } else {
        // -------- windowed attention (center query) + rel = attout @ Wo -----
        int l = blockIdx.x - L_;
        int wid = tid >> 5, lane = tid & 31;
        __shared__ float sS[2][3];
        __shared__ float sA[2][3];
        __shared__ float sat[D_];
        int nbr[3];
        nbr[0] = l > 0 ? l - 1 : 0;
        nbr[1] = l;
        nbr[2] = l < L_ - 1 ? l + 1 : L_ - 1;
        if (wid < 6) {
            int h = wid / 3, k = wid % 3;
            const float* q  = g_Q  + l * D_ + h * 150;
            const float* kk = g_Km + nbr[k] * D_ + h * 150;
            float a = 0.f;
            for (int j = lane; j < 150; j += 32) a += q[j] * kk[j];
            a = wred(a);
            if (lane == 0) sS[h][k] = a * rsqrtf(150.f);
        }
        __syncthreads();
        if (tid < 2) {
            float m = fmaxf(sS[tid][0], fmaxf(sS[tid][1], sS[tid][2]));
            float e0 = expf(sS[tid][0] - m), e1 = expf(sS[tid][1] - m), e2 = expf(sS[tid][2] - m);
            float s = e0 + e1 + e2;
            sA[tid][0] = e0 / s; sA[tid][1] = e1 / s; sA[tid][2] = e2 / s;
        }
        __syncthreads();
        for (int j = tid; j < D_; j += 640) {
            int hh = j / 150;
            float acc = 0.f;
#pragma unroll
            for (int kx = 0; kx < 3; kx++) acc += sA[hh][kx] * g_Vm[nbr[kx] * D_ + j];
            sat[j] = acc;
        }
        __syncthreads();
        // GEMV: rel[l][c] = sum_j sat[j] * Wo[j][c]
        for (int c = tid; c < D_; c += 640) {
            float a = 0.f;
#pragma unroll 8
            for (int j = 0; j < D_; j++) a += sat[j] * Wo[j * D_ + c];
            g_rel[l * D_ + c] = a;
            g_feat[l * 3 * D_ + D_ + c] = a;
        }
    }
}

// ---------------- concept attention: one block per (g,l,s) ------------------
__global__ void concept_kernel(const int* __restrict__ src_ids, const int* __restrict__ dst_ids,
                               const float* __restrict__ wgt, const float* __restrict__ sen,
                               const float* __restrict__ table, const float* __restrict__ rvecs)
{
    int u = blockIdx.x;
    int s = u % S_;
    int l = (u / S_) % L_;
    int g = u / (S_ * L_);
    int tid = threadIdx.x;              // 256 threads, 8 warps
    int lane = tid & 31, wid = tid >> 5;

    __shared__ float4 sd4[K_][D4_];
    __shared__ float4 su4[D4_];
    __shared__ float4 ssrc4[D4_];
    __shared__ float4 rv4s[D4_];
    __shared__ float du[K_], dsr[K_], dn[K_], beta[K_];
    __shared__ int   dmask[K_];
    __shared__ float red[8];
    __shared__ float s_unorm;

    int base = u * K_;
    int r0 = wid * 2, r1 = r0 + 1;
    // warp-local id fetch, no block sync needed before the gather
    int pr = (lane < 2) ? dst_ids[base + r0 + lane] : 0;
    int id0 = __shfl_sync(0xFFFFFFFFu, pr, 0);
    int id1 = __shfl_sync(0xFFFFFFFFu, pr, 1);
    if (lane < 2) dmask[r0 + lane] = (pr >= 0);
    int sid = src_ids[u];
    int smask = (sid >= 0);
    if (sid < 0) sid = 0;

    // issue gathers immediately
    const float4* d0 = (const float4*)(table + (size_t)(id0 >= 0 ? id0 : 0) * D_);
    const float4* d1 = (const float4*)(table + (size_t)(id1 >= 0 ? id1 : 0) * D_);
    bool g3 = (lane + 64) < D4_;
    float4 z4 = make_float4(0.f, 0.f, 0.f, 0.f);
    float4 v0a = d0[lane],      v1a = d1[lane];
    float4 v0b = d0[lane + 32], v1b = d1[lane + 32];
    float4 v0c = g3 ? d0[lane + 64] : z4;
    float4 v1c = g3 ? d1[lane + 64] : z4;

    // shared vectors
    const float4* rv4p = (const float4*)(rvecs + g * D_);
    if (tid < D4_) {
        float4 sv = ((const float4*)(table + (size_t)sid * D_))[tid];
        ssrc4[tid] = sv;
        rv4s[tid]  = rv4p[tid];
        su4[tid]   = ((const float4*)(g_rel + l * D_))[tid];
    }
    // stage rows to smem for phase D
    sd4[r0][lane] = v0a;  sd4[r0][lane + 32] = v0b;  if (g3) sd4[r0][lane + 64] = v0c;
    sd4[r1][lane] = v1a;  sd4[r1][lane + 32] = v1b;  if (g3) sd4[r1][lane + 64] = v1c;
    __syncthreads();

    // dots from registers against smem vectors (srp = ssrc*rv computed inline)
    {
        float4 ua = su4[lane], ub = su4[lane + 32], uc = g3 ? su4[lane + 64] : z4;
        float4 sa = ssrc4[lane], sb = ssrc4[lane + 32], sc4 = g3 ? ssrc4[lane + 64] : z4;
        float4 ra = rv4s[lane], rb = rv4s[lane + 32], rc = g3 ? rv4s[lane + 64] : z4;
        float4 pa = make_float4(sa.x * ra.x, sa.y * ra.y, sa.z * ra.z, sa.w * ra.w);
        float4 pb = make_float4(sb.x * rb.x, sb.y * rb.y, sb.z * rb.z, sb.w * rb.w);
        float4 pc = make_float4(sc4.x * rc.x, sc4.y * rc.y, sc4.z * rc.z, sc4.w * rc.w);
        float a0 = dot4(ua, v0a) + dot4(ub, v0b) + dot4(uc, v0c);
        float b0 = dot4(pa, v0a) + dot4(pb, v0b) + dot4(pc, v0c);
        float c0 = dot4(v0a, v0a) + dot4(v0b, v0b) + dot4(v0c, v0c);
        float a1 = dot4(ua, v1a) + dot4(ub, v1b) + dot4(uc, v1c);
        float b1 = dot4(pa, v1a) + dot4(pb, v1b) + dot4(pc, v1c);
        float c1 = dot4(v1a, v1a) + dot4(v1b, v1b) + dot4(v1c, v1c);
        a0 = wred(a0); b0 = wred(b0); c0 = wred(c0);
        a1 = wred(a1); b1 = wred(b1); c1 = wred(c1);
        if (lane == 0) {
            du[r0] = a0; dsr[r0] = b0; dn[r0] = c0;
            du[r1] = a1; dsr[r1] = b1; dn[r1] = c1;
        }
        if (wid == 0) {
            float p = dot4(ua, ua) + dot4(ub, ub) + dot4(uc, uc);
            p = wred(p);
            if (lane == 0) s_unorm = sqrtf(p);
        }
    }
    __syncthreads();

    // 16-lane softmax chain -> beta = alpha1 * alpha2
    if (wid == 0) {
        int k = lane & 15;
        int mk = dmask[k];
        float wk = wgt[base + k];
        float se = fabsf(sen[base + k]);
        float unorm = s_unorm;
        float cosv = fabsf(du[k]) / (unorm * sqrtf(dn[k]) + 1e-8f);
        float om = 0.5f * wk * cosv + 0.5f * se;
        float v = mk ? om : NEG_;
        float m = v;
#pragma unroll
        for (int o = 8; o; o >>= 1) m = fmaxf(m, __shfl_xor_sync(0xFFFFFFFFu, m, o));
        float e = expf(v - m);
        float sm = e;
#pragma unroll
        for (int o = 8; o; o >>= 1) sm += __shfl_xor_sync(0xFFFFFFFFu, sm, o);
        float a1v = mk ? e / sm : 0.f;

        float sv = a1v * dsr[k];
        v = mk ? sv : NEG_;
        m = v;
#pragma unroll
        for (int o = 8; o; o >>= 1) m = fmaxf(m, __shfl_xor_sync(0xFFFFFFFFu, m, o));
        e = expf(v - m);
        sm = e;
#pragma unroll
        for (int o = 8; o; o >>= 1) sm += __shfl_xor_sync(0xFFFFFFFFu, sm, o);
        float b2 = a1v * (mk ? e / sm : 0.f);
        if (lane < 16) beta[k] = b2;
    }
    __syncthreads();

    // phase D: weighted sum over rows (smem), node write + score
    const float* sdf = (const float*)sd4;
    const float* uf  = (const float*)su4;
    const float* sf  = (const float*)ssrc4;
    const float* rvf = (const float*)rv4s;
    int node = l * (3 * S_) + g * S_ + s;
    float part = 0.f;
    for (int j = tid; j < D_; j += 256) {
        float acc = 0.f;
#pragma unroll
        for (int k = 0; k < K_; k++) acc += beta[k] * sdf[k * (D4_ * 4) + j];
        float v = fmaf(rvf[j], acc, sf[j]);
        g_nodes[(size_t)node * D_ + j] = v;
        part += v * uf[j];
    }
    part = wred(part);
    if (lane == 0) red[wid] = part;
    __syncthreads();
    if (tid == 0) {
        float t = 0.f;
        for (int i = 0; i < 8; i++) t += red[i];
        g_scoreb[node] = t;
        g_nmask[node]  = smask;
    }
}

// ---------------- node attention -> sym -> feat[:,600:900] ------------------
__global__ void sym_kernel()
{
    int l = blockIdx.x;
    int tid = threadIdx.x;        // 128
    __shared__ float att[3 * S_];
    if (tid < 3 * S_)
        att[tid] = g_nmask[l * 3 * S_ + tid] ? g_scoreb[l * 3 * S_ + tid] : NEG_;
    __syncthreads();
    if (tid == 0) {
        float mx = -1e30f;
        for (int n = 0; n < 3 * S_; n++) mx = fmaxf(mx, att[n]);
        float sum = 0.f;
        for (int n = 0; n < 3 * S_; n++) { float e = expf(att[n] - mx); att[n] = e; sum += e; }
        for (int n = 0; n < 3 * S_; n++)
            att[n] = g_nmask[l * 3 * S_ + n] ? att[n] / sum : 0.f;
    }
    __syncthreads();
    if (tid < D4_) {
        float4 a = make_float4(0.f, 0.f, 0.f, 0.f);
        for (int n = 0; n < 3 * S_; n++) {
            float w = att[n];
            float4 v = ((const float4*)(g_nodes + (size_t)(l * 3 * S_ + n) * D_))[tid];
            a.x += w * v.x; a.y += w * v.y; a.z += w * v.z; a.w += w * v.w;
        }
        ((float4*)(g_feat + (size_t)l * 3 * D_ + 2 * D_))[tid] = a;
    }
}

// ---------------- final head: logits + log_softmax --------------------------
__global__ void out_kernel(const float* __restrict__ W_out, const float* __restrict__ b_out,
                           float* __restrict__ out)
{
    int l = blockIdx.x;
    int tid = threadIdx.x;        // 224 threads, 7 warps
    int wid = tid >> 5, lane = tid & 31;
    __shared__ float logit[C_];
    __shared__ float s2[2];
    float a = 0.f;
    for (int j = lane; j < D_; j += 32) a += g_h1[l * D_ + j] * W_out[j * C_ + wid];
    a = wred(a);
    if (lane == 0) logit[wid] = a + b_out[wid];
    __syncthreads();
    if (tid == 0) {
        float mx = -1e30f;
        for (int c = 0; c < C_; c++) mx = fmaxf(mx, logit[c]);
        float sum = 0.f;
        for (int c = 0; c < C_; c++) sum += expf(logit[c] - mx);
        s2[0] = mx; s2[1] = logf(sum);
    }
    __syncthreads();
    if (tid < C_) out[l * C_ + tid] = logit[tid] - s2[0] - s2[1];
}

// ---------------------------------------------------------------------------
extern "C" void kernel_launch(void* const* d_in, const int* in_sizes, int n_in,
                              void* d_out, int out_size)
{
    const float* utt      = (const float*)d_in[0];
    const int*   str_src  = (const int*)d_in[1];
    const int*   str_dst  = (const int*)d_in[2];
    const int*   str_typ  = (const int*)d_in[3];
    const int*   cpt_src  = (const int*)d_in[4];
    const int*   cpt_dst  = (const int*)d_in[5];
    const float* cpt_w    = (const float*)d_in[6];
    const float* cpt_sen  = (const float*)d_in[7];
    const float* table    = (const float*)d_in[8];
    const float* W_basis  = (const float*)d_in[9];
    const float* comp     = (const float*)d_in[10];
    const float* W_self   = (const float*)d_in[11];
    const float* b_rgcn   = (const float*)d_in[12];
    const float* Wq       = (const float*)d_in[13];
    const float* Wk       = (const float*)d_in[14];
    const float* Wv       = (const float*)d_in[15];
    const float* Wo       = (const float*)d_in[16];
    const float* r_vecs   = (const float*)d_in[17];
    const float* W_fuse   = (const float*)d_in[18];
    const float* b_fuse   = (const float*)d_in[19];
    const float* W_out    = (const float*)d_in[20];
    const float* b_out    = (const float*)d_in[21];
    float* out = (float*)d_out;

    float *Y0, *Y1, *Qb, *Kb, *Vb, *xws, *feat, *h1;
    cudaGetSymbolAddress((void**)&Y0, g_Y0);
    cudaGetSymbolAddress((void**)&Y1, g_Y1);
    cudaGetSymbolAddress((void**)&Qb, g_Q);
    cudaGetSymbolAddress((void**)&Kb, g_Km);
    cudaGetSymbolAddress((void**)&Vb, g_Vm);
    cudaGetSymbolAddress((void**)&xws, g_xws);
    cudaGetSymbolAddress((void**)&feat, g_feat);
    cudaGetSymbolAddress((void**)&h1, g_h1);

    Batch6 p;
    p.B[0] = W_basis;            p.bias[0] = nullptr; p.C[0] = Y0;
    p.B[1] = W_basis + D_ * D_;  p.bias[1] = nullptr; p.C[1] = Y1;
    p.B[2] = Wq;                 p.bias[2] = nullptr; p.C[2] = Qb;
    p.B[3] = Wk;                 p.bias[3] = nullptr; p.C[3] = Kb;
    p.B[4] = Wv;                 p.bias[4] = nullptr; p.C[4] = Vb;
    p.B[5] = W_self;             p.bias[5] = b_rgcn;  p.C[5] = xws;

    dim3 g6((D_ + 31) / 32, (L_ + 31) / 32, 6);
    gemm6_kernel<<<g6, 256>>>(utt, p);

    combo_kernel<<<2 * L_, 640>>>(str_src, str_dst, str_typ, comp, Wo);

    concept_kernel<<<3 * L_ * S_, 256>>>(cpt_src, cpt_dst, cpt_w, cpt_sen, table, r_vecs);
    sym_kernel<<<L_, 128>>>();

    dim3 gg((D_ + 31) / 32, (L_ + 31) / 32);
    gemm_kernel<<<gg, 256>>>(feat, W_fuse, b_fuse, h1, L_, D_, 3 * D_, D_, 1);
    out_kernel<<<L_, 224>>>(W_out, b_out, out);
}